// round 3
// baseline (speedup 1.0000x reference)
#include <cuda_runtime.h>

#define ALPHA   0.2f
#define NEG_BIG -9.0e15f

#define B_   8
#define N_   2048
#define F_   128

// Scratch (device globals — no allocation allowed in kernel_launch)
__device__ float g_Wh[B_ * N_ * F_];   // 32 MB
__device__ float g_s1[B_ * N_];
__device__ float g_s2[B_ * N_];

// ---------------------------------------------------------------------------
// Kernel A: Wh = h @ W.   h: [16384,128], W: [128,128] -> g_Wh [16384,128]
// 128 threads, 64-row M tile, full N=128, K chunks of 32. 8x8 register tiles.
// ---------------------------------------------------------------------------
__global__ void __launch_bounds__(128) wh_gemm(const float* __restrict__ h,
                                               const float* __restrict__ W) {
    __shared__ float hs[64][32];
    __shared__ float Ws[32][128];
    const int tid = threadIdx.x;
    const int tx = tid & 15, ty = tid >> 4;
    const int i0 = blockIdx.x * 64;

    float acc[8][8];
    #pragma unroll
    for (int r = 0; r < 8; r++)
        #pragma unroll
        for (int c = 0; c < 8; c++) acc[r][c] = 0.f;

    for (int k0 = 0; k0 < F_; k0 += 32) {
        // hs: 64x32 = 512 float4, 4 per thread
        #pragma unroll
        for (int p = 0; p < 4; p++) {
            int idx = tid + 128 * p;        // float4 index
            int r = idx >> 3;               // 8 float4 per row
            int c4 = idx & 7;
            *(float4*)&hs[r][c4 * 4] =
                *(const float4*)&h[(i0 + r) * F_ + k0 + c4 * 4];
        }
        // Ws: 32x128 = 1024 float4, 8 per thread
        #pragma unroll
        for (int p = 0; p < 8; p++) {
            int idx = tid + 128 * p;
            int r = idx >> 5;               // 32 float4 per row
            int c4 = idx & 31;
            *(float4*)&Ws[r][c4 * 4] =
                *(const float4*)&W[(k0 + r) * F_ + c4 * 4];
        }
        __syncthreads();
        #pragma unroll
        for (int kk = 0; kk < 32; kk++) {
            float av[8];
            #pragma unroll
            for (int r = 0; r < 8; r++) av[r] = hs[ty * 8 + r][kk];
            float4 b0 = *(float4*)&Ws[kk][tx * 8];
            float4 b1 = *(float4*)&Ws[kk][tx * 8 + 4];
            #pragma unroll
            for (int r = 0; r < 8; r++) {
                acc[r][0] += av[r] * b0.x; acc[r][1] += av[r] * b0.y;
                acc[r][2] += av[r] * b0.z; acc[r][3] += av[r] * b0.w;
                acc[r][4] += av[r] * b1.x; acc[r][5] += av[r] * b1.y;
                acc[r][6] += av[r] * b1.z; acc[r][7] += av[r] * b1.w;
            }
        }
        __syncthreads();
    }
    #pragma unroll
    for (int r = 0; r < 8; r++) {
        int row = i0 + ty * 8 + r;
        float4 o0 = make_float4(acc[r][0], acc[r][1], acc[r][2], acc[r][3]);
        float4 o1 = make_float4(acc[r][4], acc[r][5], acc[r][6], acc[r][7]);
        *(float4*)&g_Wh[row * F_ + tx * 8] = o0;
        *(float4*)&g_Wh[row * F_ + tx * 8 + 4] = o1;
    }
}

// ---------------------------------------------------------------------------
// Kernel B: s1[i] = Wh[i,:]·a1, s2[i] = Wh[i,:]·a2.   One warp per row.
// ---------------------------------------------------------------------------
__global__ void __launch_bounds__(256) compute_s(const float* __restrict__ a) {
    int row = blockIdx.x * 8 + (threadIdx.x >> 5);
    int lane = threadIdx.x & 31;
    float4 w  = *(const float4*)&g_Wh[row * F_ + lane * 4];
    float4 a1 = *(const float4*)&a[lane * 4];
    float4 a2 = *(const float4*)&a[F_ + lane * 4];
    float d1 = w.x * a1.x + w.y * a1.y + w.z * a1.z + w.w * a1.w;
    float d2 = w.x * a2.x + w.y * a2.y + w.z * a2.z + w.w * a2.w;
    #pragma unroll
    for (int o = 16; o > 0; o >>= 1) {
        d1 += __shfl_xor_sync(0xffffffffu, d1, o);
        d2 += __shfl_xor_sync(0xffffffffu, d2, o);
    }
    if (lane == 0) { g_s1[row] = d1; g_s2[row] = d2; }
}

// ---------------------------------------------------------------------------
// Kernel C: flash-style masked softmax aggregation.
//   CTA = (64 i-rows, one batch). Loop over 32 j-tiles of 64.
//   128 threads: ty(0..7) -> 8 rows each, tx(0..15) -> 8 feats each.
// smem: Wh tile 64x128, P tile 64x65 (padded), row state.
// ---------------------------------------------------------------------------
#define PJ 65                                    // padded P stride (bank-safe)
#define SMEM_C ((64 * 128 + 64 * PJ + 5 * 64) * 4)

__global__ void __launch_bounds__(128) gat_attn(const int* __restrict__ adj,
                                                float* __restrict__ out) {
    extern __shared__ float sm[];
    float* Whs = sm;                             // [64][128]
    float* P   = sm + 64 * 128;                  // [64][PJ]
    float* s1s = P + 64 * PJ;                    // [64]
    float* s2s = s1s + 64;
    float* ms  = s2s + 64;
    float* ls  = ms + 64;
    float* scs = ls + 64;

    const int tid = threadIdx.x;
    const int tx = tid & 15, ty = tid >> 4;
    const int b = blockIdx.y;
    const int i0 = blockIdx.x * 64;
    const float* WhB = g_Wh + b * N_ * F_;

    if (tid < 64) {
        s1s[tid] = g_s1[b * N_ + i0 + tid];
        ms[tid] = NEG_BIG;
        ls[tid] = 0.f;
    }

    float acc[8][8];
    #pragma unroll
    for (int r = 0; r < 8; r++)
        #pragma unroll
        for (int c = 0; c < 8; c++) acc[r][c] = 0.f;

    for (int jt = 0; jt < N_ / 64; jt++) {
        const int j0 = jt * 64;
        // Wh tile: 64x128 = 2048 float4, 16 per thread
        #pragma unroll
        for (int p = 0; p < 16; p++) {
            int idx = tid + 128 * p;
            int r = idx >> 5;
            int c4 = idx & 31;
            *(float4*)&Whs[r * 128 + c4 * 4] =
                *(const float4*)&WhB[(j0 + r) * F_ + c4 * 4];
        }
        if (tid < 64) s2s[tid] = g_s2[b * N_ + j0 + tid];
        __syncthreads();

        // Scores: 4096 entries, 32 per thread; coalesced adj reads.
        #pragma unroll
        for (int k = 0; k < 32; k++) {
            int e = tid + 128 * k;
            int i = e >> 6;
            int j = e & 63;
            float raw = s1s[i] + s2s[j];
            float lr = raw > 0.f ? raw : ALPHA * raw;
            int ad = adj[(i0 + i) * N_ + j0 + j];
            P[i * PJ + j] = (ad > 0) ? lr : NEG_BIG;
        }
        __syncthreads();

        // Online softmax update: one thread per row.
        if (tid < 64) {
            const int i = tid;
            float m_old = ms[i];
            float tmax = NEG_BIG;
            #pragma unroll 8
            for (int j = 0; j < 64; j++) tmax = fmaxf(tmax, P[i * PJ + j]);
            float mnew = fmaxf(m_old, tmax);
            float rs = 0.f;
            #pragma unroll 8
            for (int j = 0; j < 64; j++) {
                float pv = __expf(P[i * PJ + j] - mnew);
                P[i * PJ + j] = pv;
                rs += pv;
            }
            float sc = __expf(m_old - mnew);
            ls[i] = ls[i] * sc + rs;
            ms[i] = mnew;
            scs[i] = sc;
        }
        __syncthreads();

        // Rescale accumulators, then P(64x64) @ WhTile(64x128) outer-product.
        float sc[8];
        #pragma unroll
        for (int r = 0; r < 8; r++) sc[r] = scs[ty * 8 + r];
        #pragma unroll
        for (int r = 0; r < 8; r++)
            #pragma unroll
            for (int c = 0; c < 8; c++) acc[r][c] *= sc[r];

        #pragma unroll 4
        for (int jj = 0; jj < 64; jj++) {
            float pr[8];
            #pragma unroll
            for (int r = 0; r < 8; r++) pr[r] = P[(ty * 8 + r) * PJ + jj];
            float4 w0 = *(float4*)&Whs[jj * 128 + tx * 8];
            float4 w1 = *(float4*)&Whs[jj * 128 + tx * 8 + 4];
            #pragma unroll
            for (int r = 0; r < 8; r++) {
                acc[r][0] += pr[r] * w0.x; acc[r][1] += pr[r] * w0.y;
                acc[r][2] += pr[r] * w0.z; acc[r][3] += pr[r] * w0.w;
                acc[r][4] += pr[r] * w1.x; acc[r][5] += pr[r] * w1.y;
                acc[r][6] += pr[r] * w1.z; acc[r][7] += pr[r] * w1.w;
            }
        }
        __syncthreads();
    }

    // Epilogue: divide by l, write out.
    #pragma unroll
    for (int r = 0; r < 8; r++) {
        int i = ty * 8 + r;
        float inv = 1.f / ls[i];
        int row = b * N_ + i0 + i;
        float4 o0 = make_float4(acc[r][0] * inv, acc[r][1] * inv,
                                acc[r][2] * inv, acc[r][3] * inv);
        float4 o1 = make_float4(acc[r][4] * inv, acc[r][5] * inv,
                                acc[r][6] * inv, acc[r][7] * inv);
        *(float4*)&out[row * F_ + tx * 8] = o0;
        *(float4*)&out[row * F_ + tx * 8 + 4] = o1;
    }
}

// ---------------------------------------------------------------------------
extern "C" void kernel_launch(void* const* d_in, const int* in_sizes, int n_in,
                              void* d_out, int out_size) {
    const float* h   = (const float*)d_in[0];   // [8,2048,128]
    const int*   adj = (const int*)d_in[1];     // [2048,2048]
    const float* W   = (const float*)d_in[2];   // [128,128]
    const float* a   = (const float*)d_in[3];   // [256,1]
    float* out = (float*)d_out;                 // [8,2048,128]

    (void)in_sizes; (void)n_in; (void)out_size;

    static bool attr_set = false;
    if (!attr_set) {
        cudaFuncSetAttribute(gat_attn,
                             cudaFuncAttributeMaxDynamicSharedMemorySize,
                             SMEM_C);
        attr_set = true;
    }

    wh_gemm<<<(B_ * N_) / 64, 128>>>(h, W);
    compute_s<<<(B_ * N_) / 8, 256>>>(a);
    gat_attn<<<dim3(N_ / 64, B_), 128, SMEM_C>>>(adj, out);
}